// round 8
// baseline (speedup 1.0000x reference)
#include <cuda_runtime.h>
#include <cuda_bf16.h>
#include <cstdint>

// Problem constants
#define BC      16            // B*C = 8*2
#define LL      2048
#define TSZ     17
#define PAD     8
#define KPAD    16            // MMA covers taps 0..15; tap 16 exact in fp32

__device__ __forceinline__ float to_tf32(float v) {
    uint32_t b;
    asm("cvt.rna.tf32.f32 %0, %1;" : "=r"(b) : "f"(v));
    return __uint_as_float(b);
}

// m16n8k8 tf32 MMA (sm_80+ baseline; valid on plain sm_103 target)
__device__ __forceinline__ void mma_tf32(float* c,
                                         uint32_t a0, uint32_t a1, uint32_t a2, uint32_t a3,
                                         uint32_t b0, uint32_t b1) {
    asm volatile(
        "mma.sync.aligned.m16n8k8.row.col.f32.tf32.tf32.f32 "
        "{%0,%1,%2,%3}, {%4,%5,%6,%7}, {%8,%9}, {%0,%1,%2,%3};"
        : "+f"(c[0]), "+f"(c[1]), "+f"(c[2]), "+f"(c[3])
        : "r"(a0), "r"(a1), "r"(a2), "r"(a3), "r"(b0), "r"(b1));
}

// ================== Single fused kernel ==================
// CTA tile: 64(l) x 128(m).  out[l][m] = sum_t xf[l][t] * x[m+t-8]
//  Phase 1: load x windows + filter into smem.
//  Phase 2: compute xf[64][17] in-CTA (fma pipe), tf32 hi/lo split -> smem A planes.
//  Phase 3: 3xTF32 mma.sync GEMM (taps 0..15) + exact fp32 tap-16 rank-1 update.
// 8 warps: wy(2, l) x wx(4, m); warp tile 32x32 = 2 mf x 4 nf fragments (acc 32 regs).
#define ASTRIDE 20            // A smem row stride (conflict-free fragment reads)
#define WINLEN  160           // m-window arrays (152 used)
#define XLLEN   80            // l-window (64 + 16)

__global__ void __launch_bounds__(256, 3)
filter_fused_kernel(const float* __restrict__ x, const float* __restrict__ filt,
                    float* __restrict__ out) {
    __shared__ float As_hi[64 * ASTRIDE];
    __shared__ float As_lo[64 * ASTRIDE];
    __shared__ float win_h[WINLEN];
    __shared__ float win_l[WINLEN];
    __shared__ float win_f[WINLEN];
    __shared__ float xl[XLLEN];
    __shared__ float sfilt[TSZ * TSZ];
    __shared__ float sxf16[64];

    const int tid = threadIdx.x;
    const int wid = tid >> 5;
    const int lane = tid & 31;
    const int g   = lane >> 2;    // 0..7
    const int tig = lane & 3;     // 0..3
    const int wy = wid >> 2;      // 0..1  (l)
    const int wx = wid & 3;       // 0..3  (m)

    const int bc = blockIdx.z;
    const int l0 = blockIdx.y * 64;
    const int m0 = blockIdx.x * 128;
    const int c  = bc & 1;

    // ---------- Phase 1: smem fills ----------
    if (tid < 152) {
        int gi = m0 + tid - PAD;
        float v = (gi >= 0 && gi < LL) ? x[bc * LL + gi] : 0.0f;
        float hi = to_tf32(v);
        win_f[tid] = v;
        win_h[tid] = hi;
        win_l[tid] = to_tf32(v - hi);
    }
    if (tid >= 160 && tid < 160 + XLLEN) {
        int i = tid - 160;
        int gi = l0 + i - PAD;
        xl[i] = (gi >= 0 && gi < LL) ? x[bc * LL + gi] : 0.0f;
    }
    for (int i = tid; i < TSZ * TSZ; i += 256)
        sfilt[i] = filt[c * TSZ * TSZ + i];
    __syncthreads();

    // ---------- Phase 2: xf compute, tf32 split, -> A planes ----------
    // thread (r = tid>>2, tg = tid&3) computes taps 4tg..4tg+3 of row r
    {
        const int r  = tid >> 2;
        const int t0 = (tid & 3) * 4;
        float a4[4] = {0.0f, 0.0f, 0.0f, 0.0f};
#pragma unroll
        for (int s = 0; s < TSZ; s++) {
            float xv = xl[r + s];
            const float* fr = &sfilt[s * TSZ + t0];
            a4[0] += xv * fr[0];
            a4[1] += xv * fr[1];
            a4[2] += xv * fr[2];
            a4[3] += xv * fr[3];
        }
        float h0 = to_tf32(a4[0]), h1 = to_tf32(a4[1]);
        float h2 = to_tf32(a4[2]), h3 = to_tf32(a4[3]);
        *reinterpret_cast<float4*>(&As_hi[r * ASTRIDE + t0]) = make_float4(h0, h1, h2, h3);
        *reinterpret_cast<float4*>(&As_lo[r * ASTRIDE + t0]) =
            make_float4(to_tf32(a4[0] - h0), to_tf32(a4[1] - h1),
                        to_tf32(a4[2] - h2), to_tf32(a4[3] - h3));
    }
    // tap 16 (full fp32) by threads 0..63
    if (tid < 64) {
        float a16 = 0.0f;
#pragma unroll
        for (int s = 0; s < TSZ; s++)
            a16 += xl[tid + s] * sfilt[s * TSZ + 16];
        sxf16[tid] = a16;
    }
    __syncthreads();

    // ---------- Phase 3: MMA ----------
    float acc[2][4][4];
#pragma unroll
    for (int mf = 0; mf < 2; mf++)
#pragma unroll
        for (int nf = 0; nf < 4; nf++)
#pragma unroll
            for (int j = 0; j < 4; j++) acc[mf][nf][j] = 0.0f;

    const int rbase = wy * 32 + g;            // A fragment row base (local l)
    const int wbase = wx * 32 + g + tig;      // B hoist base

    // bb[j] = wp[wbase + 4j]; fragment (nf,kt): b0=bb[2(nf+kt)], b1=bb[2(nf+kt)+1]
    float bb[10];

#pragma unroll
    for (int p = 0; p < 3; p++) {
        // pass order: AhBh, AlBh, AhBl (Bh regs live passes 0-1)
        const float* Ap = (p == 1) ? As_lo : As_hi;
        if (p == 0) {
#pragma unroll
            for (int j = 0; j < 10; j++) bb[j] = win_h[wbase + 4 * j];
        } else if (p == 2) {
#pragma unroll
            for (int j = 0; j < 10; j++) bb[j] = win_l[wbase + 4 * j];
        }
#pragma unroll
        for (int kt = 0; kt < 2; kt++) {
            const int kb = kt * 8 + tig;
#pragma unroll
            for (int mf = 0; mf < 2; mf++) {
                const float* ar = Ap + (rbase + mf * 16) * ASTRIDE + kb;
                uint32_t a0 = __float_as_uint(ar[0]);
                uint32_t a1 = __float_as_uint(ar[8 * ASTRIDE]);
                uint32_t a2 = __float_as_uint(ar[4]);
                uint32_t a3 = __float_as_uint(ar[8 * ASTRIDE + 4]);
#pragma unroll
                for (int nf = 0; nf < 4; nf++)
                    mma_tf32(acc[mf][nf],
                             a0, a1, a2, a3,
                             __float_as_uint(bb[2 * (nf + kt)]),
                             __float_as_uint(bb[2 * (nf + kt) + 1]));
            }
        }
    }

    // ---- exact tap-16 rank-1 update (fma pipe) ----
    {
        float a16[2][2];
#pragma unroll
        for (int mf = 0; mf < 2; mf++) {
            a16[mf][0] = sxf16[rbase + mf * 16];
            a16[mf][1] = sxf16[rbase + mf * 16 + 8];
        }
#pragma unroll
        for (int nf = 0; nf < 4; nf++) {
            int cb = wx * 32 + nf * 8 + 2 * tig + 16;
            float bf0 = win_f[cb];
            float bf1 = win_f[cb + 1];
#pragma unroll
            for (int mf = 0; mf < 2; mf++) {
                acc[mf][nf][0] += a16[mf][0] * bf0;
                acc[mf][nf][1] += a16[mf][0] * bf1;
                acc[mf][nf][2] += a16[mf][1] * bf0;
                acc[mf][nf][3] += a16[mf][1] * bf1;
            }
        }
    }

    // ---- store: fragment-layout st.v2 ----
#pragma unroll
    for (int mf = 0; mf < 2; mf++) {
        int row = l0 + rbase + mf * 16;
#pragma unroll
        for (int nf = 0; nf < 4; nf++) {
            int col = m0 + wx * 32 + nf * 8 + 2 * tig;
            float* p0 = out + (size_t)(bc * LL + row) * LL + col;
            float* p1 = p0 + (size_t)8 * LL;
            *reinterpret_cast<float2*>(p0) = make_float2(acc[mf][nf][0], acc[mf][nf][1]);
            *reinterpret_cast<float2*>(p1) = make_float2(acc[mf][nf][2], acc[mf][nf][3]);
        }
    }
}

extern "C" void kernel_launch(void* const* d_in, const int* in_sizes, int n_in,
                              void* d_out, int out_size) {
    const float* x    = (const float*)d_in[0];   // [8,2,2048]
    const float* filt = (const float*)d_in[1];   // [1,2,17,17]
    float* out = (float*)d_out;                  // [8,2,2048,2048]

    dim3 grid(LL / 128, LL / 64, BC);
    filter_fused_kernel<<<grid, 256>>>(x, filt, out);
}

// round 10
// speedup vs baseline: 1.2680x; 1.2680x over previous
#include <cuda_runtime.h>
#include <cuda_bf16.h>
#include <cstdint>

// Problem constants
#define BC      16            // B*C = 8*2
#define LL      2048
#define TSZ     17
#define PAD     8
#define KPAD    16            // MMA covers taps 0..15; tap 16 exact in fp32

// tf32 hi/lo planes of xf (taps 0..15): [bc][l][16]
__device__ float g_xf_hi[BC * LL * KPAD];
__device__ float g_xf_lo[BC * LL * KPAD];
__device__ float g_xf16[BC * LL];          // tap 16, full fp32

__device__ __forceinline__ float to_tf32(float v) {
    uint32_t b;
    asm("cvt.rna.tf32.f32 %0, %1;" : "=r"(b) : "f"(v));
    return __uint_as_float(b);
}

// m16n8k8 tf32 MMA (sm_80+ baseline; valid on plain sm_103 target)
__device__ __forceinline__ void mma_tf32(float* c,
                                         uint32_t a0, uint32_t a1, uint32_t a2, uint32_t a3,
                                         uint32_t b0, uint32_t b1) {
    asm volatile(
        "mma.sync.aligned.m16n8k8.row.col.f32.tf32.tf32.f32 "
        "{%0,%1,%2,%3}, {%4,%5,%6,%7}, {%8,%9}, {%0,%1,%2,%3};"
        : "+f"(c[0]), "+f"(c[1]), "+f"(c[2]), "+f"(c[3])
        : "r"(a0), "r"(a1), "r"(a2), "r"(a3), "r"(b0), "r"(b1));
}

// ============ Kernel 0: xf build, 4 threads per l-row ============
// thread (row, tq) computes taps 4tq..4tq+3; tq==0 also computes tap 16.
__global__ void build_xf_kernel(const float* __restrict__ x,
                                const float* __restrict__ filt) {
    __shared__ float sf[TSZ * TSZ];
    __shared__ float sxw[80];             // x window for this block's 64 rows

    const int tid = threadIdx.x;
    const int gid = blockIdx.x * 256 + tid;
    const int tq  = gid & 3;
    const int row = gid >> 2;             // bc*LL + l
    const int bc  = row >> 11;
    const int c   = bc & 1;
    const int lr  = row & 63;             // row within block (64 rows/block)
    const int blk_l0 = (row & 2047) - lr; // first l of this block (within bc)

    for (int i = tid; i < TSZ * TSZ; i += 256)
        sf[i] = filt[c * TSZ * TSZ + i];
    if (tid < 80) {
        int gi = blk_l0 + tid - PAD;
        sxw[tid] = (gi >= 0 && gi < LL) ? x[bc * LL + gi] : 0.0f;
    }
    __syncthreads();

    const int t0 = tq * 4;
    float a4[4] = {0.0f, 0.0f, 0.0f, 0.0f};
    float a16 = 0.0f;
#pragma unroll
    for (int s = 0; s < TSZ; s++) {
        float xv = sxw[lr + s];
        const float* fr = &sf[s * TSZ + t0];
        a4[0] += xv * fr[0];
        a4[1] += xv * fr[1];
        a4[2] += xv * fr[2];
        a4[3] += xv * fr[3];
        if (tq == 0) a16 += xv * sf[s * TSZ + 16];
    }

    float h0 = to_tf32(a4[0]), h1 = to_tf32(a4[1]);
    float h2 = to_tf32(a4[2]), h3 = to_tf32(a4[3]);
    reinterpret_cast<float4*>(g_xf_hi)[row * 4 + tq] = make_float4(h0, h1, h2, h3);
    reinterpret_cast<float4*>(g_xf_lo)[row * 4 + tq] =
        make_float4(to_tf32(a4[0] - h0), to_tf32(a4[1] - h1),
                    to_tf32(a4[2] - h2), to_tf32(a4[3] - h3));
    if (tq == 0) g_xf16[row] = a16;
}

// ============ Kernel 1: mma.sync tf32 GEMM + exact tap-16 + staged epilogue ============
// D[128(l),128(m)] = A[128,16]*B[16,128] (3xTF32) + xf16[l]*x[m+8] (fp32)
// 8 warps: wy(4,l) x wx(2,m); warp tile 32(l) x 64(m) = 2 mf x 8 nf.
#define ASTRIDE 20            // A smem row stride (conflict-free fragment reads)
#define SSTRIDE 72            // epilogue stage row stride (conflict-free STS.64 + LDS.128)

__global__ void __launch_bounds__(256, 2)
filter_mma_kernel(const float* __restrict__ x, float* __restrict__ out) {
    __shared__ float pool[5120];          // As_hi[2560] | As_lo[2560]; reused as stage
    __shared__ float win_h[160];
    __shared__ float win_l[160];
    __shared__ float win_f[160];
    __shared__ float sxf16[128];

    float* As_hi = pool;
    float* As_lo = pool + 2560;

    const int tid = threadIdx.x;
    const int wid = tid >> 5;
    const int lane = tid & 31;
    const int g   = lane >> 2;    // 0..7
    const int tig = lane & 3;     // 0..3
    const int wy = wid >> 1;      // 0..3  (l)
    const int wx = wid & 1;       // 0..1  (m)

    const int bc = blockIdx.z;
    const int l0 = blockIdx.y * 128;
    const int m0 = blockIdx.x * 128;

    // ---- x window: win[i] = x[bc][m0 + i - 8] ----
    if (tid < 152) {
        int gi = m0 + tid - PAD;
        float v = (gi >= 0 && gi < LL) ? x[bc * LL + gi] : 0.0f;
        float hi = to_tf32(v);
        win_f[tid] = v;
        win_h[tid] = hi;
        win_l[tid] = to_tf32(v - hi);
    }
    if (tid < 128)
        sxf16[tid] = g_xf16[bc * LL + l0 + tid];

    // ---- A fill: [128][16] gmem -> smem stride 20, float4 ----
    {
        const float4* gh = reinterpret_cast<const float4*>(g_xf_hi) + (size_t)(bc * LL + l0) * 4;
        const float4* gl = reinterpret_cast<const float4*>(g_xf_lo) + (size_t)(bc * LL + l0) * 4;
#pragma unroll
        for (int it = 0; it < 2; it++) {
            int f4 = it * 256 + tid;          // 0..511
            int row = f4 >> 2, q = f4 & 3;
            *reinterpret_cast<float4*>(&As_hi[row * ASTRIDE + q * 4]) = gh[f4];
            *reinterpret_cast<float4*>(&As_lo[row * ASTRIDE + q * 4]) = gl[f4];
        }
    }
    __syncthreads();

    // ---- accumulators: 2 mf x 8 nf x 4 ----
    float acc[2][8][4];
#pragma unroll
    for (int mf = 0; mf < 2; mf++)
#pragma unroll
        for (int nf = 0; nf < 8; nf++)
#pragma unroll
            for (int j = 0; j < 4; j++) acc[mf][nf][j] = 0.0f;

    const int rbase = wy * 32 + g;            // A fragment row base (local l)
    const int wbase = wx * 64 + g + tig;      // B hoist base

    float bb[18];                             // bb[j] = wp[wbase + 4j]

#pragma unroll
    for (int p = 0; p < 3; p++) {
        // pass order: AhBh, AlBh, AhBl (Bh regs live passes 0-1)
        const float* Ap = (p == 1) ? As_lo : As_hi;
        if (p == 0) {
#pragma unroll
            for (int j = 0; j < 18; j++) bb[j] = win_h[wbase + 4 * j];
        } else if (p == 2) {
#pragma unroll
            for (int j = 0; j < 18; j++) bb[j] = win_l[wbase + 4 * j];
        }
#pragma unroll
        for (int kt = 0; kt < 2; kt++) {
            const int kb = kt * 8 + tig;
#pragma unroll
            for (int mf = 0; mf < 2; mf++) {
                const float* ar = Ap + (rbase + mf * 16) * ASTRIDE + kb;
                uint32_t a0 = __float_as_uint(ar[0]);
                uint32_t a1 = __float_as_uint(ar[8 * ASTRIDE]);
                uint32_t a2 = __float_as_uint(ar[4]);
                uint32_t a3 = __float_as_uint(ar[8 * ASTRIDE + 4]);
#pragma unroll
                for (int nf = 0; nf < 8; nf++)
                    mma_tf32(acc[mf][nf],
                             a0, a1, a2, a3,
                             __float_as_uint(bb[2 * (nf + kt)]),
                             __float_as_uint(bb[2 * (nf + kt) + 1]));
            }
        }
    }

    // ---- exact tap-16 rank-1 update (fma pipe) ----
    {
        float a16[2][2];
#pragma unroll
        for (int mf = 0; mf < 2; mf++) {
            a16[mf][0] = sxf16[rbase + mf * 16];
            a16[mf][1] = sxf16[rbase + mf * 16 + 8];
        }
#pragma unroll
        for (int nf = 0; nf < 8; nf++) {
            int cb = wx * 64 + nf * 8 + 2 * tig + 16;
            float bf0 = win_f[cb];
            float bf1 = win_f[cb + 1];
#pragma unroll
            for (int mf = 0; mf < 2; mf++) {
                acc[mf][nf][0] += a16[mf][0] * bf0;
                acc[mf][nf][1] += a16[mf][0] * bf1;
                acc[mf][nf][2] += a16[mf][1] * bf0;
                acc[mf][nf][3] += a16[mf][1] * bf1;
            }
        }
    }

    // ---- staged epilogue: per-warp smem transpose -> coalesced STG.128 ----
    __syncthreads();                      // all A reads done; reuse pool
    float* stg = pool + wid * (8 * SSTRIDE);   // 576 floats/warp (4608 total)
    const int r2  = lane >> 4;            // 0..1
    const int c16 = lane & 15;            // 0..15
    const int colg = m0 + wx * 64 + c16 * 4;

#pragma unroll
    for (int mf = 0; mf < 2; mf++) {
#pragma unroll
        for (int h = 0; h < 2; h++) {
            // STS: 8 rows (g) x 64 cols; stride 72 -> conflict-free st.v2
#pragma unroll
            for (int nf = 0; nf < 8; nf++)
                *reinterpret_cast<float2*>(&stg[g * SSTRIDE + nf * 8 + 2 * tig]) =
                    make_float2(acc[mf][nf][2 * h], acc[mf][nf][2 * h + 1]);
            __syncwarp();
            const int rowbase = l0 + wy * 32 + mf * 16 + 8 * h;
#pragma unroll
            for (int i = 0; i < 4; i++) {
                int rr = r2 + 2 * i;
                float4 v = *reinterpret_cast<const float4*>(&stg[rr * SSTRIDE + c16 * 4]);
                *reinterpret_cast<float4*>(
                    out + (size_t)(bc * LL + rowbase + rr) * LL + colg) = v;
            }
            __syncwarp();
        }
    }
}

extern "C" void kernel_launch(void* const* d_in, const int* in_sizes, int n_in,
                              void* d_out, int out_size) {
    const float* x    = (const float*)d_in[0];   // [8,2,2048]
    const float* filt = (const float*)d_in[1];   // [1,2,17,17]
    float* out = (float*)d_out;                  // [8,2,2048,2048]

    build_xf_kernel<<<(BC * LL * 4) / 256, 256>>>(x, filt);

    dim3 grid(LL / 128, LL / 128, BC);
    filter_mma_kernel<<<grid, 256>>>(x, out);
}

// round 12
// speedup vs baseline: 1.5581x; 1.2288x over previous
#include <cuda_runtime.h>
#include <cuda_bf16.h>
#include <cstdint>

// Problem constants
#define BC      16            // B*C = 8*2
#define LL      2048
#define TSZ     17
#define PAD     8
#define KPAD    16            // MMA covers taps 0..15; tap 16 exact in fp32

// tf32 plane of xf (taps 0..15): [bc][l][16]  (single plane; B is split instead)
__device__ float g_xf_hi[BC * LL * KPAD];
__device__ float g_xf16[BC * LL];          // tap 16, full fp32

__device__ __forceinline__ float to_tf32(float v) {
    uint32_t b;
    asm("cvt.rna.tf32.f32 %0, %1;" : "=r"(b) : "f"(v));
    return __uint_as_float(b);
}

// m16n8k8 tf32 MMA (sm_80+ baseline; valid on plain sm_103 target)
__device__ __forceinline__ void mma_tf32(float* c,
                                         uint32_t a0, uint32_t a1, uint32_t a2, uint32_t a3,
                                         uint32_t b0, uint32_t b1) {
    asm volatile(
        "mma.sync.aligned.m16n8k8.row.col.f32.tf32.tf32.f32 "
        "{%0,%1,%2,%3}, {%4,%5,%6,%7}, {%8,%9}, {%0,%1,%2,%3};"
        : "+f"(c[0]), "+f"(c[1]), "+f"(c[2]), "+f"(c[3])
        : "r"(a0), "r"(a1), "r"(a2), "r"(a3), "r"(b0), "r"(b1));
}

// ============ Kernel 0: xf build, 4 threads per l-row ============
__global__ void build_xf_kernel(const float* __restrict__ x,
                                const float* __restrict__ filt) {
    __shared__ float sf[TSZ * TSZ];
    __shared__ float sxw[80];

    const int tid = threadIdx.x;
    const int gid = blockIdx.x * 256 + tid;
    const int tq  = gid & 3;
    const int row = gid >> 2;             // bc*LL + l
    const int bc  = row >> 11;
    const int c   = bc & 1;
    const int lr  = row & 63;
    const int blk_l0 = (row & 2047) - lr;

    for (int i = tid; i < TSZ * TSZ; i += 256)
        sf[i] = filt[c * TSZ * TSZ + i];
    if (tid < 80) {
        int gi = blk_l0 + tid - PAD;
        sxw[tid] = (gi >= 0 && gi < LL) ? x[bc * LL + gi] : 0.0f;
    }
    __syncthreads();

    const int t0 = tq * 4;
    float a4[4] = {0.0f, 0.0f, 0.0f, 0.0f};
    float a16 = 0.0f;
#pragma unroll
    for (int s = 0; s < TSZ; s++) {
        float xv = sxw[lr + s];
        const float* fr = &sf[s * TSZ + t0];
        a4[0] += xv * fr[0];
        a4[1] += xv * fr[1];
        a4[2] += xv * fr[2];
        a4[3] += xv * fr[3];
        if (tq == 0) a16 += xv * sf[s * TSZ + 16];
    }

    reinterpret_cast<float4*>(g_xf_hi)[row * 4 + tq] =
        make_float4(to_tf32(a4[0]), to_tf32(a4[1]), to_tf32(a4[2]), to_tf32(a4[3]));
    if (tq == 0) g_xf16[row] = a16;
}

// ============ Kernel 1: 2-pass split-B tf32 GEMM + exact tap-16 + staged epilogue ============
// D[128(l),128(m)] = Ah[128,16]*(Bh+Bl)[16,128] + xf16[l]*x[m+8] (fp32)
// 8 warps: wy(4,l) x wx(2,m); warp tile 32(l) x 64(m) = 2 mf x 8 nf.
#define ASTRIDE 20            // A smem row stride (conflict-free fragment reads)
#define SSTRIDE 72            // epilogue stage row stride (conflict-free STS.64 + LDS.128)

__global__ void __launch_bounds__(256, 2)
filter_mma_kernel(const float* __restrict__ x, float* __restrict__ out) {
    __shared__ float pool[4608];          // As[2560] during mainloop; stage[4608] after
    __shared__ float win_h[160];
    __shared__ float win_l[160];
    __shared__ float win_f[160];
    __shared__ float sxf16[128];

    float* As = pool;

    const int tid = threadIdx.x;
    const int wid = tid >> 5;
    const int lane = tid & 31;
    const int g   = lane >> 2;    // 0..7
    const int tig = lane & 3;     // 0..3
    const int wy = wid >> 1;      // 0..3  (l)
    const int wx = wid & 1;       // 0..1  (m)

    const int bc = blockIdx.z;
    const int l0 = blockIdx.y * 128;
    const int m0 = blockIdx.x * 128;

    // ---- x window: win[i] = x[bc][m0 + i - 8], fp32 + tf32 hi/lo split ----
    if (tid < 152) {
        int gi = m0 + tid - PAD;
        float v = (gi >= 0 && gi < LL) ? x[bc * LL + gi] : 0.0f;
        float hi = to_tf32(v);
        win_f[tid] = v;
        win_h[tid] = hi;
        win_l[tid] = to_tf32(v - hi);
    }
    if (tid < 128)
        sxf16[tid] = g_xf16[bc * LL + l0 + tid];

    // ---- A fill: [128][16] gmem -> smem stride 20, float4 ----
    {
        const float4* gh = reinterpret_cast<const float4*>(g_xf_hi) + (size_t)(bc * LL + l0) * 4;
#pragma unroll
        for (int it = 0; it < 2; it++) {
            int f4 = it * 256 + tid;          // 0..511
            int row = f4 >> 2, q = f4 & 3;
            *reinterpret_cast<float4*>(&As[row * ASTRIDE + q * 4]) = gh[f4];
        }
    }
    __syncthreads();

    // ---- accumulators: 2 mf x 8 nf x 4 ----
    float acc[2][8][4];
#pragma unroll
    for (int mf = 0; mf < 2; mf++)
#pragma unroll
        for (int nf = 0; nf < 8; nf++)
#pragma unroll
            for (int j = 0; j < 4; j++) acc[mf][nf][j] = 0.0f;

    const int rbase = wy * 32 + g;            // A fragment row base (local l)
    const int wbase = wx * 64 + g + tig;      // B hoist base

    // ---- A fragments hoisted ONCE (identical across both passes) ----
    uint32_t af[2][2][4];                     // [kt][mf][a0..a3]
#pragma unroll
    for (int kt = 0; kt < 2; kt++) {
        const int kb = kt * 8 + tig;
#pragma unroll
        for (int mf = 0; mf < 2; mf++) {
            const float* ar = As + (rbase + mf * 16) * ASTRIDE + kb;
            af[kt][mf][0] = __float_as_uint(ar[0]);
            af[kt][mf][1] = __float_as_uint(ar[8 * ASTRIDE]);
            af[kt][mf][2] = __float_as_uint(ar[4]);
            af[kt][mf][3] = __float_as_uint(ar[8 * ASTRIDE + 4]);
        }
    }

    float bb[18];                             // bb[j] = wp[wbase + 4j]
#pragma unroll
    for (int p = 0; p < 2; p++) {
        const float* wp = (p == 0) ? win_h : win_l;
#pragma unroll
        for (int j = 0; j < 18; j++) bb[j] = wp[wbase + 4 * j];
#pragma unroll
        for (int kt = 0; kt < 2; kt++) {
#pragma unroll
            for (int mf = 0; mf < 2; mf++) {
#pragma unroll
                for (int nf = 0; nf < 8; nf++)
                    mma_tf32(acc[mf][nf],
                             af[kt][mf][0], af[kt][mf][1], af[kt][mf][2], af[kt][mf][3],
                             __float_as_uint(bb[2 * (nf + kt)]),
                             __float_as_uint(bb[2 * (nf + kt) + 1]));
            }
        }
    }

    // ---- exact tap-16 rank-1 update (fma pipe) ----
    {
        float a16[2][2];
#pragma unroll
        for (int mf = 0; mf < 2; mf++) {
            a16[mf][0] = sxf16[rbase + mf * 16];
            a16[mf][1] = sxf16[rbase + mf * 16 + 8];
        }
#pragma unroll
        for (int nf = 0; nf < 8; nf++) {
            int cb = wx * 64 + nf * 8 + 2 * tig + 16;
            float bf0 = win_f[cb];
            float bf1 = win_f[cb + 1];
#pragma unroll
            for (int mf = 0; mf < 2; mf++) {
                acc[mf][nf][0] += a16[mf][0] * bf0;
                acc[mf][nf][1] += a16[mf][0] * bf1;
                acc[mf][nf][2] += a16[mf][1] * bf0;
                acc[mf][nf][3] += a16[mf][1] * bf1;
            }
        }
    }

    // ---- staged epilogue: per-warp smem transpose -> coalesced STG.128 ----
    __syncthreads();                      // A reads done; reuse pool as stage
    float* stg = pool + wid * (8 * SSTRIDE);
    const int r2  = lane >> 4;            // 0..1
    const int c16 = lane & 15;            // 0..15
    const int colg = m0 + wx * 64 + c16 * 4;

#pragma unroll
    for (int mf = 0; mf < 2; mf++) {
#pragma unroll
        for (int h = 0; h < 2; h++) {
#pragma unroll
            for (int nf = 0; nf < 8; nf++)
                *reinterpret_cast<float2*>(&stg[g * SSTRIDE + nf * 8 + 2 * tig]) =
                    make_float2(acc[mf][nf][2 * h], acc[mf][nf][2 * h + 1]);
            __syncwarp();
            const int rowbase = l0 + wy * 32 + mf * 16 + 8 * h;
#pragma unroll
            for (int i = 0; i < 4; i++) {
                int rr = r2 + 2 * i;
                float4 v = *reinterpret_cast<const float4*>(&stg[rr * SSTRIDE + c16 * 4]);
                *reinterpret_cast<float4*>(
                    out + (size_t)(bc * LL + rowbase + rr) * LL + colg) = v;
            }
            __syncwarp();
        }
    }
}

extern "C" void kernel_launch(void* const* d_in, const int* in_sizes, int n_in,
                              void* d_out, int out_size) {
    const float* x    = (const float*)d_in[0];   // [8,2,2048]
    const float* filt = (const float*)d_in[1];   // [1,2,17,17]
    float* out = (float*)d_out;                  // [8,2,2048,2048]

    build_xf_kernel<<<(BC * LL * 4) / 256, 256>>>(x, filt);

    dim3 grid(LL / 128, LL / 128, BC);
    filter_mma_kernel<<<grid, 256>>>(x, out);
}

// round 13
// speedup vs baseline: 1.6607x; 1.0659x over previous
#include <cuda_runtime.h>
#include <cuda_bf16.h>
#include <cstdint>

// Problem constants
#define BC      16            // B*C = 8*2
#define LL      2048
#define TSZ     17
#define PAD     8
#define KPAD    16            // MMA covers taps 0..15; tap 16 exact in fp32

// tf32 plane of xf (taps 0..15): [bc][l][16]  (single plane; B split supplies precision)
__device__ float g_xf_hi[BC * LL * KPAD];
__device__ float g_xf16[BC * LL];          // tap 16, full fp32

__device__ __forceinline__ float to_tf32(float v) {
    uint32_t b;
    asm("cvt.rna.tf32.f32 %0, %1;" : "=r"(b) : "f"(v));
    return __uint_as_float(b);
}

// m16n8k8 tf32 MMA (sm_80+ baseline; valid on plain sm_103 target)
__device__ __forceinline__ void mma_tf32(float* c,
                                         uint32_t a0, uint32_t a1, uint32_t a2, uint32_t a3,
                                         uint32_t b0, uint32_t b1) {
    asm volatile(
        "mma.sync.aligned.m16n8k8.row.col.f32.tf32.tf32.f32 "
        "{%0,%1,%2,%3}, {%4,%5,%6,%7}, {%8,%9}, {%0,%1,%2,%3};"
        : "+f"(c[0]), "+f"(c[1]), "+f"(c[2]), "+f"(c[3])
        : "r"(a0), "r"(a1), "r"(a2), "r"(a3), "r"(b0), "r"(b1));
}

// ============ Kernel 0: xf build, 4 threads per l-row ============
__global__ void build_xf_kernel(const float* __restrict__ x,
                                const float* __restrict__ filt) {
    __shared__ float sf[TSZ * TSZ];
    __shared__ float sxw[80];

    const int tid = threadIdx.x;
    const int gid = blockIdx.x * 256 + tid;
    const int tq  = gid & 3;
    const int row = gid >> 2;             // bc*LL + l
    const int bc  = row >> 11;
    const int c   = bc & 1;
    const int lr  = row & 63;
    const int blk_l0 = (row & 2047) - lr;

    for (int i = tid; i < TSZ * TSZ; i += 256)
        sf[i] = filt[c * TSZ * TSZ + i];
    if (tid < 80) {
        int gi = blk_l0 + tid - PAD;
        sxw[tid] = (gi >= 0 && gi < LL) ? x[bc * LL + gi] : 0.0f;
    }
    __syncthreads();

    const int t0 = tq * 4;
    float a4[4] = {0.0f, 0.0f, 0.0f, 0.0f};
    float a16 = 0.0f;
#pragma unroll
    for (int s = 0; s < TSZ; s++) {
        float xv = sxw[lr + s];
        const float* fr = &sf[s * TSZ + t0];
        a4[0] += xv * fr[0];
        a4[1] += xv * fr[1];
        a4[2] += xv * fr[2];
        a4[3] += xv * fr[3];
        if (tq == 0) a16 += xv * sf[s * TSZ + 16];
    }

    reinterpret_cast<float4*>(g_xf_hi)[row * 4 + tq] =
        make_float4(to_tf32(a4[0]), to_tf32(a4[1]), to_tf32(a4[2]), to_tf32(a4[3]));
    if (tq == 0) g_xf16[row] = a16;
}

// ============ Kernel 1: 2-pass split-B tf32 GEMM, sequential 32-col halves ============
// D[128(l),128(m)] = Ah[128,16]*(Bh+Bl)[16,128] + xf16[l]*x[m+8] (fp32)
// 8 warps: wy(4,l) x wx(2,m); warp covers 32(l) x 64(m), processed as two
// 32x32 halves (acc 32 regs live) -> ~85 regs -> 3 CTAs/SM.
#define ASTRIDE 20            // A smem row stride (conflict-free fragment reads)
#define SSTRIDE 40            // stage row stride (conflict-free STS.64 + LDS.128)

__global__ void __launch_bounds__(256, 3)
filter_mma_kernel(const float* __restrict__ x, float* __restrict__ out) {
    __shared__ float pool[4608];          // As[2560] (until af hoist); stage[2560] after
    __shared__ float win_h[160];
    __shared__ float win_l[160];
    __shared__ float win_f[160];
    __shared__ float sxf16[128];

    float* As = pool;

    const int tid = threadIdx.x;
    const int wid = tid >> 5;
    const int lane = tid & 31;
    const int g   = lane >> 2;    // 0..7
    const int tig = lane & 3;     // 0..3
    const int wy = wid >> 1;      // 0..3  (l)
    const int wx = wid & 1;       // 0..1  (m)

    const int bc = blockIdx.z;
    const int l0 = blockIdx.y * 128;
    const int m0 = blockIdx.x * 128;

    // ---- x window: win[i] = x[bc][m0 + i - 8], fp32 + tf32 hi/lo split ----
    if (tid < 152) {
        int gi = m0 + tid - PAD;
        float v = (gi >= 0 && gi < LL) ? x[bc * LL + gi] : 0.0f;
        float hi = to_tf32(v);
        win_f[tid] = v;
        win_h[tid] = hi;
        win_l[tid] = to_tf32(v - hi);
    }
    if (tid < 128)
        sxf16[tid] = g_xf16[bc * LL + l0 + tid];

    // ---- A fill: [128][16] gmem -> smem stride 20, float4 ----
    {
        const float4* gh = reinterpret_cast<const float4*>(g_xf_hi) + (size_t)(bc * LL + l0) * 4;
#pragma unroll
        for (int it = 0; it < 2; it++) {
            int f4 = it * 256 + tid;          // 0..511
            int row = f4 >> 2, q = f4 & 3;
            *reinterpret_cast<float4*>(&As[row * ASTRIDE + q * 4]) = gh[f4];
        }
    }
    __syncthreads();

    const int rbase = wy * 32 + g;            // A fragment row base (local l)

    // ---- A fragments hoisted ONCE (shared by both passes and both halves) ----
    uint32_t af[2][2][4];                     // [kt][mf][a0..a3]
#pragma unroll
    for (int kt = 0; kt < 2; kt++) {
        const int kb = kt * 8 + tig;
#pragma unroll
        for (int mf = 0; mf < 2; mf++) {
            const float* ar = As + (rbase + mf * 16) * ASTRIDE + kb;
            af[kt][mf][0] = __float_as_uint(ar[0]);
            af[kt][mf][1] = __float_as_uint(ar[8 * ASTRIDE]);
            af[kt][mf][2] = __float_as_uint(ar[4]);
            af[kt][mf][3] = __float_as_uint(ar[8 * ASTRIDE + 4]);
        }
    }
    __syncthreads();                      // all As reads done; pool becomes stage

    float* stg = pool + wid * (8 * SSTRIDE);   // 320 floats per warp
    const int r4 = lane >> 3;             // 0..3
    const int c8 = lane & 7;              // 0..7

    float a16[2][2];
#pragma unroll
    for (int mf = 0; mf < 2; mf++) {
        a16[mf][0] = sxf16[rbase + mf * 16];
        a16[mf][1] = sxf16[rbase + mf * 16 + 8];
    }

    // ================== two sequential 32-col halves ==================
#pragma unroll 1
    for (int half = 0; half < 2; half++) {
        const int mh = wx * 64 + half * 32;   // m offset within CTA tile
        const int wbase = mh + g + tig;       // B hoist base

        float acc[2][4][4];
#pragma unroll
        for (int mf = 0; mf < 2; mf++)
#pragma unroll
            for (int nf = 0; nf < 4; nf++)
#pragma unroll
                for (int j = 0; j < 4; j++) acc[mf][nf][j] = 0.0f;

        float bb[10];                         // bb[j] = wp[wbase + 4j]
#pragma unroll
        for (int p = 0; p < 2; p++) {
            const float* wp = (p == 0) ? win_h : win_l;
#pragma unroll
            for (int j = 0; j < 10; j++) bb[j] = wp[wbase + 4 * j];
#pragma unroll
            for (int kt = 0; kt < 2; kt++) {
#pragma unroll
                for (int mf = 0; mf < 2; mf++) {
#pragma unroll
                    for (int nf = 0; nf < 4; nf++)
                        mma_tf32(acc[mf][nf],
                                 af[kt][mf][0], af[kt][mf][1], af[kt][mf][2], af[kt][mf][3],
                                 __float_as_uint(bb[2 * (nf + kt)]),
                                 __float_as_uint(bb[2 * (nf + kt) + 1]));
                }
            }
        }

        // ---- exact tap-16 rank-1 update (fma pipe) ----
#pragma unroll
        for (int nf = 0; nf < 4; nf++) {
            int cb = mh + nf * 8 + 2 * tig + 16;
            float bf0 = win_f[cb];
            float bf1 = win_f[cb + 1];
#pragma unroll
            for (int mf = 0; mf < 2; mf++) {
                acc[mf][nf][0] += a16[mf][0] * bf0;
                acc[mf][nf][1] += a16[mf][0] * bf1;
                acc[mf][nf][2] += a16[mf][1] * bf0;
                acc[mf][nf][3] += a16[mf][1] * bf1;
            }
        }

        // ---- staged epilogue: per-warp smem transpose -> coalesced STG.128 ----
        const int colg = m0 + mh + c8 * 4;
#pragma unroll
        for (int mf = 0; mf < 2; mf++) {
#pragma unroll
            for (int h = 0; h < 2; h++) {
                // STS: 8 rows (g) x 32 cols; stride 40 -> conflict-free st.v2
#pragma unroll
                for (int nf = 0; nf < 4; nf++)
                    *reinterpret_cast<float2*>(&stg[g * SSTRIDE + nf * 8 + 2 * tig]) =
                        make_float2(acc[mf][nf][2 * h], acc[mf][nf][2 * h + 1]);
                __syncwarp();
                const int rowbase = l0 + wy * 32 + mf * 16 + 8 * h;
#pragma unroll
                for (int i = 0; i < 2; i++) {
                    int rr = r4 + 4 * i;
                    float4 v = *reinterpret_cast<const float4*>(&stg[rr * SSTRIDE + c8 * 4]);
                    *reinterpret_cast<float4*>(
                        out + (size_t)(bc * LL + rowbase + rr) * LL + colg) = v;
                }
                __syncwarp();
            }
        }
    }
}

extern "C" void kernel_launch(void* const* d_in, const int* in_sizes, int n_in,
                              void* d_out, int out_size) {
    const float* x    = (const float*)d_in[0];   // [8,2,2048]
    const float* filt = (const float*)d_in[1];   // [1,2,17,17]
    float* out = (float*)d_out;                  // [8,2,2048,2048]

    build_xf_kernel<<<(BC * LL * 4) / 256, 256>>>(x, filt);

    dim3 grid(LL / 128, LL / 128, BC);
    filter_mma_kernel<<<grid, 256>>>(x, out);
}